// round 10
// baseline (speedup 1.0000x reference)
#include <cuda_runtime.h>

#define TT   1000
#define HH   4096
#define PP   16
#define NCTA 8           // one cluster of 8 CTAs
#define TPB  128         // 4 warps; 4 neurons/thread: 8*128*4 = 4096
#define NW   (TPB / 32)
#define NN   4           // neurons per thread

// Scratch (device globals; no allocation). Rewritten identically every replay.
__device__ float g_pre[TT * HH];   // Win@x + noise/10
__device__ float g_r[TT * HH];     // r_t[h] trace (consumed by y_kernel)

// ---- PTX helpers ------------------------------------------------------------
__device__ __forceinline__ unsigned smem_u32(const void* p) {
    return (unsigned)__cvta_generic_to_shared(p);
}
__device__ __forceinline__ unsigned mapa_sh(unsigned local, unsigned rank) {
    unsigned r;
    asm volatile("mapa.shared::cluster.u32 %0, %1, %2;" : "=r"(r) : "r"(local), "r"(rank));
    return r;
}
__device__ __forceinline__ void st_cluster_f32(unsigned addr, float v) {
    asm volatile("st.shared::cluster.f32 [%0], %1;" :: "r"(addr), "f"(v) : "memory");
}
__device__ __forceinline__ void st_rel_cluster_u32(unsigned addr, unsigned v) {
    asm volatile("st.release.cluster.shared::cluster.u32 [%0], %1;"
                 :: "r"(addr), "r"(v) : "memory");
}
__device__ __forceinline__ unsigned ld_acq_cluster(unsigned addr) {
    unsigned v;
    asm volatile("ld.acquire.cluster.shared::cta.u32 %0, [%1];"
                 : "=r"(v) : "r"(addr) : "memory");
    return v;
}
__device__ __forceinline__ void cluster_sync() {
    asm volatile("barrier.cluster.arrive.aligned;" ::: "memory");
    asm volatile("barrier.cluster.wait.aligned;" ::: "memory");
}
__device__ __forceinline__ unsigned ctarank() {
    unsigned r; asm("mov.u32 %0, %%cluster_ctarank;" : "=r"(r)); return r;
}
#define BAR_ARRIVE(id, n) asm volatile("bar.arrive %0, %1;" :: "r"(id), "r"(n) : "memory")
#define BAR_SYNC(id, n)   asm volatile("bar.sync %0, %1;"   :: "r"(id), "r"(n) : "memory")

// Warp-wide reduction of 32 per-lane values in 31 shuffles (5 dependent
// levels). On return, value j (summed over all lanes) is held by lane j.
__device__ __forceinline__ float fold32(float v[32], int lane) {
#pragma unroll
    for (int m = 16; m >= 1; m >>= 1) {
        const bool hi = (lane & m) != 0;
#pragma unroll
        for (int i = 0; i < m; i++) {
            float keep = hi ? v[i + m] : v[i];
            float send = hi ? v[i] : v[i + m];
            float recv = __shfl_xor_sync(0xffffffffu, send, m);
            v[i] = keep + recv;
        }
    }
    return v[0];
}

// pre[t][h] = Win[h,:]@x[t,:] + noise[t,h]/10
__global__ void pre_kernel(const float* __restrict__ noise,
                           const float* __restrict__ x,
                           const float* __restrict__ Win)
{
    int i = blockIdx.x * blockDim.x + threadIdx.x;
    if (i < TT * HH) {
        int t = i / HH, h = i - t * HH;
        float acc = noise[i] * 0.1f;
        const float* wr = &Win[h * 6];
        const float* xr = &x[t * 6];
#pragma unroll
        for (int k = 0; k < 6; k++) acc += wr[k] * xr[k];
        g_pre[i] = acc;
    }
}

// Peer-visible shared layout (fixed offsets: peer addr = peer_base + offset).
struct alignas(128) ShMsg {
    float    msg[2][NCTA][32];    // [A_t(0..15) | B_{t+1}(16..31)] per producer
    unsigned flg[2][NCTA];        // monotonic tags
};

__global__ void __launch_bounds__(TPB, 1) __cluster_dims__(NCTA, 1, 1)
snn_scan(const float* __restrict__ pin,    // [H,16]
         const float* __restrict__ pout,   // [H,16]
         const float* __restrict__ l,      // [16]
         const float* __restrict__ stau)   // [H]
{
    const int tid  = threadIdx.x;
    const int lane = tid & 31;
    const int warp = tid >> 5;
    const unsigned rank = ctarank();

    __shared__ ShMsg sh;
    __shared__ __align__(128) float part[2][NW][32];   // local-only

    if (tid < 2 * NCTA) ((unsigned*)sh.flg)[tid] = 0u;
    __syncthreads();
    cluster_sync();   // zero-init visible before any remote store

    const unsigned base_local = smem_u32(&sh);
    unsigned pb[NCTA];
#pragma unroll
    for (int c = 0; c < NCTA; c++) pb[c] = mapa_sh(base_local, (unsigned)c);

    const unsigned MSG0 = 0u;
    const unsigned FLG0 = (unsigned)(2 * NCTA * 32 * 4);

    // ---- per-neuron constants (x4) in registers ----
    const float drc    = 0.08208499862389880f;   // exp(-DT/TAU_R)
    const float c005dr = 0.005f * drc;

    int hh[NN];
    float dd[NN], sg[NN], ic[NN];
    float lp[NN][PP], kA[NN][PP];
#pragma unroll
    for (int k = 0; k < NN; k++) {
        hh[k] = (int)rank * TPB + tid + k * (NCTA * TPB);
        const float tau = 1.0f / (1.0f + expf(-stau[hh[k]])) * 0.03f + 0.02f;
        dd[k] = expf(-0.005f / tau);
        sg[k] = 2.5f / tau;                 // DT/(tau*TAU_R)
        ic[k] = tau * 80.0f;                // 1/(DT*sg)
#pragma unroll
        for (int p = 0; p < PP; p++) {
            lp[k][p] = l[p] * pin[hh[k] * PP + p];
            kA[k][p] = pout[hh[k] * PP + p] * (0.0125f / tau);   // po*DT*sg
        }
    }

    float mem[NN], rr[NN], ss[NN], pre[NN], preN[NN];
#pragma unroll
    for (int k = 0; k < NN; k++) {
        mem[k] = 0.f; rr[k] = 0.f; ss[k] = 0.f;
        pre[k]  = g_pre[hh[k]];           // t = 0
        preN[k] = g_pre[HH + hh[k]];      // t = 1 (prefetch depth 2)
    }
    float bprev = 0.f;            // lanes 0..15: cluster-wide B_t; B_0 = 0

    const unsigned flg_local = base_local + FLG0;

    for (int t = 0; t < TT; t++) {
        // ============ consume: q_t = A_{t-1} + B_{t-1} (local smem) ========
        float q = 0.f;
        if (t > 0) {
            const int sl = (t - 1) & 1;
            if (lane < NCTA) {
                const unsigned fa = flg_local + (unsigned)(sl * NCTA + lane) * 4u;
                while (ld_acq_cluster(fa) != (unsigned)t) {}
            }
            __syncwarp();
            const float* m = &sh.msg[sl][0][lane];
            float s0 = (m[0 * 32] + m[1 * 32]) + (m[2 * 32] + m[3 * 32]);
            float s1 = (m[4 * 32] + m[5 * 32]) + (m[6 * 32] + m[7 * 32]);
            float sum  = s0 + s1;                      // 0-15: ΣA, 16-31: ΣB_next
            float bnew = __shfl_down_sync(0xffffffffu, sum, 16);
            q = sum + bprev;                           // valid in lanes 0..15
            bprev = bnew;
        }

        // ============ I and membrane update (4 neurons) ====================
        float acc0[NN], acc1[NN];
#pragma unroll
        for (int k = 0; k < NN; k++) { acc0[k] = pre[k]; acc1[k] = 0.f; }
#pragma unroll
        for (int p = 0; p < 8; p++) {
            const float qa = __shfl_sync(0xffffffffu, q, p);
            const float qb = __shfl_sync(0xffffffffu, q, p + 8);
#pragma unroll
            for (int k = 0; k < NN; k++) {
                acc0[k] += lp[k][p] * qa;
                acc1[k] += lp[k][p + 8] * qb;
            }
        }
        float f[NN], rbn[NN];
#pragma unroll
        for (int k = 0; k < NN; k++) {
            mem[k] = 0.9f * mem[k] + (acc0[k] + acc1[k])
                   - ((mem[k] > 0.5f) ? 0.5f : 0.0f);
            f[k]   = (mem[k] > 0.5f) ? 1.0f : 0.0f;
            ss[k]  = ss[k] * drc + f[k] * sg[k];
            rr[k]  = dd[k] * rr[k] + 0.005f * ss[k];
            rbn[k] = (dd[k] * rr[k] + c005dr * ss[k]) * ic[k];  // rbar_{t+1}/(DT*sg)
        }

        // ============ fold + hand off partial ==============================
        float v[32];
#pragma unroll
        for (int p = 0; p < PP; p++) {
            v[p]      = (f[0] * kA[0][p] + f[1] * kA[1][p])
                      + (f[2] * kA[2][p] + f[3] * kA[3][p]);        // A_t
            v[16 + p] = (rbn[0] * kA[0][p] + rbn[1] * kA[1][p])
                      + (rbn[2] * kA[2][p] + rbn[3] * kA[3][p]);    // B_{t+1}
        }
        part[t & 1][warp][lane] = fold32(v, lane);

        if (warp != NW - 1) {
            BAR_ARRIVE(1, TPB);       // hand off, don't stall
        } else {
            // Publisher = HIGHEST warp: hi-wid-first arbiter gives the serial
            // hub warp issue priority in its SMSP.
            BAR_SYNC(1, TPB);         // wait for all partials (drains STS)
            const float* pp = &part[t & 1][0][lane];
            const float accm = (pp[0 * 32] + pp[1 * 32]) + (pp[2 * 32] + pp[3 * 32]);

            // push my 128B message into every cluster CTA's smem
            const unsigned moff = MSG0
                + (unsigned)(((t & 1) * NCTA + (int)rank) * 32 + lane) * 4u;
#pragma unroll
            for (int c = 0; c < NCTA; c++)
                st_cluster_f32(pb[c] + moff, accm);
            __syncwarp();             // all lanes' data stores before the flags
            if (lane < NCTA) {
                const unsigned foff = FLG0
                    + (unsigned)((t & 1) * NCTA + (int)rank) * 4u;
                st_rel_cluster_u32(pb[lane] + foff, (unsigned)(t + 1));
            }
        }

        // ======== slack: r trace + rotate prefetch (depth 2) ==============
        const int tn = (t + 2 < TT) ? (t + 2) : (TT - 1);
#pragma unroll
        for (int k = 0; k < NN; k++) {
            g_r[t * HH + hh[k]] = rr[k];
            pre[k]  = preN[k];
            preN[k] = g_pre[tn * HH + hh[k]];
        }
    }

    // No CTA may exit while peers' remote stores are in flight.
    cluster_sync();
}

// y[t,o] = Wout[o,:] @ r[t,:]  — one block per timestep, deterministic order.
__global__ void __launch_bounds__(256) y_kernel(const float* __restrict__ Wout,
                                                float* __restrict__ out)
{
    const int t   = blockIdx.x;
    const int tid = threadIdx.x;
    const int lane = tid & 31, warp = tid >> 5;
    float y0 = 0.f, y1 = 0.f;
#pragma unroll
    for (int j = 0; j < HH / 256; j++) {
        const int h  = tid + j * 256;
        const float rv = g_r[t * HH + h];
        y0 += Wout[h] * rv;
        y1 += Wout[HH + h] * rv;
    }
#pragma unroll
    for (int o = 16; o > 0; o >>= 1) {
        y0 += __shfl_xor_sync(0xffffffffu, y0, o);
        y1 += __shfl_xor_sync(0xffffffffu, y1, o);
    }
    __shared__ float s0[8], s1[8];
    if (lane == 0) { s0[warp] = y0; s1[warp] = y1; }
    __syncthreads();
    if (tid == 0) {
        float a0 = 0.f, a1 = 0.f;
#pragma unroll
        for (int w = 0; w < 8; w++) { a0 += s0[w]; a1 += s1[w]; }
        out[t * 2 + 0] = a0;
        out[t * 2 + 1] = a1;
    }
}

extern "C" void kernel_launch(void* const* d_in, const int* in_sizes, int n_in,
                              void* d_out, int out_size)
{
    const float* x     = (const float*)d_in[0];
    const float* noise = (const float*)d_in[1];
    const float* Win   = (const float*)d_in[2];
    const float* Wout  = (const float*)d_in[3];
    const float* pin   = (const float*)d_in[4];
    const float* pout  = (const float*)d_in[5];
    const float* l     = (const float*)d_in[6];
    const float* stau  = (const float*)d_in[7];
    float* out = (float*)d_out;

    pre_kernel<<<(TT * HH + 255) / 256, 256>>>(noise, x, Win);
    snn_scan<<<NCTA, TPB>>>(pin, pout, l, stau);
    y_kernel<<<TT, 256>>>(Wout, out);
}

// round 11
// speedup vs baseline: 1.2241x; 1.2241x over previous
#include <cuda_runtime.h>

#define TT   1000
#define HH   4096
#define PP   16
#define NCTA 8           // one cluster of 8 CTAs
#define TPB  128         // 4 warps; 4 neurons/thread: 8*128*4 = 4096
#define NW   (TPB / 32)
#define NN   4           // neurons per thread

// Scratch (device globals; no allocation). Rewritten identically every replay.
__device__ float g_pre[TT * HH];   // Win@x + noise/10
__device__ float g_r[TT * HH];     // r_t[h] trace (consumed by y_kernel)

// ---- PTX helpers ------------------------------------------------------------
__device__ __forceinline__ unsigned smem_u32(const void* p) {
    return (unsigned)__cvta_generic_to_shared(p);
}
__device__ __forceinline__ unsigned mapa_sh(unsigned local, unsigned rank) {
    unsigned r;
    asm volatile("mapa.shared::cluster.u32 %0, %1, %2;" : "=r"(r) : "r"(local), "r"(rank));
    return r;
}
__device__ __forceinline__ void st_cluster_f32(unsigned addr, float v) {
    asm volatile("st.shared::cluster.f32 [%0], %1;" :: "r"(addr), "f"(v) : "memory");
}
__device__ __forceinline__ void st_rel_cluster_u32(unsigned addr, unsigned v) {
    asm volatile("st.release.cluster.shared::cluster.u32 [%0], %1;"
                 :: "r"(addr), "r"(v) : "memory");
}
__device__ __forceinline__ unsigned ld_acq_cluster(unsigned addr) {
    unsigned v;
    asm volatile("ld.acquire.cluster.shared::cta.u32 %0, [%1];"
                 : "=r"(v) : "r"(addr) : "memory");
    return v;
}
__device__ __forceinline__ void cluster_sync() {
    asm volatile("barrier.cluster.arrive.aligned;" ::: "memory");
    asm volatile("barrier.cluster.wait.aligned;" ::: "memory");
}
__device__ __forceinline__ unsigned ctarank() {
    unsigned r; asm("mov.u32 %0, %%cluster_ctarank;" : "=r"(r)); return r;
}

// Warp-wide reduction of 32 per-lane values in 31 shuffles (5 dependent
// levels). On return, value j (summed over all lanes) is held by lane j.
__device__ __forceinline__ float fold32(float v[32], int lane) {
#pragma unroll
    for (int m = 16; m >= 1; m >>= 1) {
        const bool hi = (lane & m) != 0;
#pragma unroll
        for (int i = 0; i < m; i++) {
            float keep = hi ? v[i + m] : v[i];
            float send = hi ? v[i] : v[i + m];
            float recv = __shfl_xor_sync(0xffffffffu, send, m);
            v[i] = keep + recv;
        }
    }
    return v[0];
}

// pre[t][h] = Win[h,:]@x[t,:] + noise[t,h]/10
__global__ void pre_kernel(const float* __restrict__ noise,
                           const float* __restrict__ x,
                           const float* __restrict__ Win)
{
    int i = blockIdx.x * blockDim.x + threadIdx.x;
    if (i < TT * HH) {
        int t = i / HH, h = i - t * HH;
        float acc = noise[i] * 0.1f;
        const float* wr = &Win[h * 6];
        const float* xr = &x[t * 6];
#pragma unroll
        for (int k = 0; k < 6; k++) acc += wr[k] * xr[k];
        g_pre[i] = acc;
    }
}

// Peer-visible shared layout (fixed offsets: peer addr = peer_base + offset).
struct alignas(128) ShMsg {
    float    msg[2][NCTA][32];    // [A_t(0..15) | B_{t+1}(16..31)] per producer
    unsigned flg[2][NCTA];        // monotonic tags
};

__global__ void __launch_bounds__(TPB, 1) __cluster_dims__(NCTA, 1, 1)
snn_scan(const float* __restrict__ pin,    // [H,16]
         const float* __restrict__ pout,   // [H,16]
         const float* __restrict__ l,      // [16]
         const float* __restrict__ stau)   // [H]
{
    const int tid  = threadIdx.x;
    const int lane = tid & 31;
    const int warp = tid >> 5;
    const unsigned rank = ctarank();

    __shared__ ShMsg sh;
    __shared__ __align__(128) float part[2][NW][32];   // local-only

    if (tid < 2 * NCTA) ((unsigned*)sh.flg)[tid] = 0u;
    __syncthreads();
    cluster_sync();   // zero-init visible before any remote store

    const unsigned msg_base = smem_u32(&sh.msg[0][0][0]);
    const unsigned flg_base = smem_u32(&sh.flg[0][0]);

    // ---- per-neuron constants (x4) in registers ----
    const float drc    = 0.08208499862389880f;   // exp(-DT/TAU_R)
    const float c005dr = 0.005f * drc;

    int hh[NN];
    float dd[NN], sg[NN], ic[NN];
    float lp[NN][PP], kA[NN][PP];
#pragma unroll
    for (int k = 0; k < NN; k++) {
        hh[k] = (int)rank * TPB + tid + k * (NCTA * TPB);
        const float tau = 1.0f / (1.0f + expf(-stau[hh[k]])) * 0.03f + 0.02f;
        dd[k] = expf(-0.005f / tau);
        sg[k] = 2.5f / tau;                 // DT/(tau*TAU_R)
        ic[k] = tau * 80.0f;                // 1/(DT*sg)
#pragma unroll
        for (int p = 0; p < PP; p++) {
            lp[k][p] = l[p] * pin[hh[k] * PP + p];
            kA[k][p] = pout[hh[k] * PP + p] * (0.0125f / tau);   // po*DT*sg
        }
    }

    float mem[NN], rr[NN], ss[NN], pre[NN];
#pragma unroll
    for (int k = 0; k < NN; k++) {
        mem[k] = 0.f; rr[k] = 0.f; ss[k] = 0.f;
        pre[k] = g_pre[hh[k]];    // t = 0
    }
    float bprev = 0.f;            // lanes 0..15: cluster-wide B_t; B_0 = 0

    for (int t = 0; t < TT; t++) {
        // ============ consume: q_t = A_{t-1} + B_{t-1} (local smem) ========
        float q = 0.f;
        if (t > 0) {
            const int sl = (t - 1) & 1;
            if (lane < NCTA) {
                const unsigned fa = flg_base + (unsigned)(sl * NCTA + lane) * 4u;
                while (ld_acq_cluster(fa) != (unsigned)t) {}
            }
            __syncwarp();
            const float* m = &sh.msg[sl][0][lane];
            float s0 = (m[0 * 32] + m[1 * 32]) + (m[2 * 32] + m[3 * 32]);
            float s1 = (m[4 * 32] + m[5 * 32]) + (m[6 * 32] + m[7 * 32]);
            float sum  = s0 + s1;                      // 0-15: ΣA, 16-31: ΣB_next
            float bnew = __shfl_down_sync(0xffffffffu, sum, 16);
            q = sum + bprev;                           // valid in lanes 0..15
            bprev = bnew;
        }

        // ============ I and membrane update (4 neurons) ====================
        float acc0[NN], acc1[NN];
#pragma unroll
        for (int k = 0; k < NN; k++) { acc0[k] = pre[k]; acc1[k] = 0.f; }
#pragma unroll
        for (int p = 0; p < 8; p++) {
            const float qa = __shfl_sync(0xffffffffu, q, p);
            const float qb = __shfl_sync(0xffffffffu, q, p + 8);
#pragma unroll
            for (int k = 0; k < NN; k++) {
                acc0[k] += lp[k][p] * qa;
                acc1[k] += lp[k][p + 8] * qb;
            }
        }
        float f[NN], rbn[NN];
#pragma unroll
        for (int k = 0; k < NN; k++) {
            mem[k] = 0.9f * mem[k] + (acc0[k] + acc1[k])
                   - ((mem[k] > 0.5f) ? 0.5f : 0.0f);
            f[k]   = (mem[k] > 0.5f) ? 1.0f : 0.0f;
            ss[k]  = ss[k] * drc + f[k] * sg[k];
            rr[k]  = dd[k] * rr[k] + 0.005f * ss[k];
            rbn[k] = (dd[k] * rr[k] + c005dr * ss[k]) * ic[k];  // rbar_{t+1}/(DT*sg)
        }

        // ============ fold ================================================
        float v[32];
#pragma unroll
        for (int p = 0; p < PP; p++) {
            v[p]      = (f[0] * kA[0][p] + f[1] * kA[1][p])
                      + (f[2] * kA[2][p] + f[3] * kA[3][p]);        // A_t
            v[16 + p] = (rbn[0] * kA[0][p] + rbn[1] * kA[1][p])
                      + (rbn[2] * kA[2][p] + rbn[3] * kA[3][p]);    // B_{t+1}
        }
        part[t & 1][warp][lane] = fold32(v, lane);

        // ============ distributed publish: warp w -> peers 2w, 2w+1 ========
        __syncthreads();   // all partials visible (drains STS)
        {
            const float* pp = &part[t & 1][0][lane];
            // identical combine in every warp (deterministic, bit-identical)
            const float accm = (pp[0 * 32] + pp[1 * 32]) + (pp[2 * 32] + pp[3 * 32]);

            const unsigned my_msg = msg_base
                + (unsigned)(((t & 1) * NCTA + (int)rank) * 32 + lane) * 4u;
            const unsigned c0 = (unsigned)(warp * 2);
            st_cluster_f32(mapa_sh(my_msg, c0),      accm);
            st_cluster_f32(mapa_sh(my_msg, c0 + 1u), accm);
            __syncwarp();          // this warp's data stores before its flags
            if (lane < 2) {
                const unsigned my_flg = flg_base
                    + (unsigned)((t & 1) * NCTA + (int)rank) * 4u;
                st_rel_cluster_u32(mapa_sh(my_flg, c0 + (unsigned)lane),
                                   (unsigned)(t + 1));
            }
        }

        // ======== slack: r trace + prefetch next input ====================
        const int tn = (t + 1 < TT) ? (t + 1) : t;
#pragma unroll
        for (int k = 0; k < NN; k++) {
            g_r[t * HH + hh[k]] = rr[k];
            pre[k] = g_pre[tn * HH + hh[k]];
        }
    }

    // No CTA may exit while peers' remote stores are in flight.
    cluster_sync();
}

// y[t,o] = Wout[o,:] @ r[t,:]  — one block per timestep, deterministic order.
__global__ void __launch_bounds__(256) y_kernel(const float* __restrict__ Wout,
                                                float* __restrict__ out)
{
    const int t   = blockIdx.x;
    const int tid = threadIdx.x;
    const int lane = tid & 31, warp = tid >> 5;
    float y0 = 0.f, y1 = 0.f;
#pragma unroll
    for (int j = 0; j < HH / 256; j++) {
        const int h  = tid + j * 256;
        const float rv = g_r[t * HH + h];
        y0 += Wout[h] * rv;
        y1 += Wout[HH + h] * rv;
    }
#pragma unroll
    for (int o = 16; o > 0; o >>= 1) {
        y0 += __shfl_xor_sync(0xffffffffu, y0, o);
        y1 += __shfl_xor_sync(0xffffffffu, y1, o);
    }
    __shared__ float s0[8], s1[8];
    if (lane == 0) { s0[warp] = y0; s1[warp] = y1; }
    __syncthreads();
    if (tid == 0) {
        float a0 = 0.f, a1 = 0.f;
#pragma unroll
        for (int w = 0; w < 8; w++) { a0 += s0[w]; a1 += s1[w]; }
        out[t * 2 + 0] = a0;
        out[t * 2 + 1] = a1;
    }
}

extern "C" void kernel_launch(void* const* d_in, const int* in_sizes, int n_in,
                              void* d_out, int out_size)
{
    const float* x     = (const float*)d_in[0];
    const float* noise = (const float*)d_in[1];
    const float* Win   = (const float*)d_in[2];
    const float* Wout  = (const float*)d_in[3];
    const float* pin   = (const float*)d_in[4];
    const float* pout  = (const float*)d_in[5];
    const float* l     = (const float*)d_in[6];
    const float* stau  = (const float*)d_in[7];
    float* out = (float*)d_out;

    pre_kernel<<<(TT * HH + 255) / 256, 256>>>(noise, x, Win);
    snn_scan<<<NCTA, TPB>>>(pin, pout, l, stau);
    y_kernel<<<TT, 256>>>(Wout, out);
}

// round 13
// speedup vs baseline: 1.3014x; 1.0631x over previous
#include <cuda_runtime.h>

#define TT   1000
#define HH   4096
#define PP   16
#define NCTA 8           // one cluster of 8 CTAs
#define TPB  128         // 4 warps; 4 neurons/thread: 8*128*4 = 4096
#define NW   (TPB / 32)
#define NN   4           // neurons per thread

// Scratch (device globals; no allocation). Rewritten identically every replay.
__device__ float g_pre[TT * HH];   // Win@x + noise/10
__device__ float g_r[TT * HH];     // r_t[h] trace (consumed by y_kernel)

// ---- PTX helpers ------------------------------------------------------------
__device__ __forceinline__ unsigned smem_u32(const void* p) {
    return (unsigned)__cvta_generic_to_shared(p);
}
__device__ __forceinline__ unsigned mapa_sh(unsigned local, unsigned rank) {
    unsigned r;
    asm volatile("mapa.shared::cluster.u32 %0, %1, %2;" : "=r"(r) : "r"(local), "r"(rank));
    return r;
}
__device__ __forceinline__ void st_cluster_f32(unsigned addr, float v) {
    asm volatile("st.shared::cluster.f32 [%0], %1;" :: "r"(addr), "f"(v) : "memory");
}
__device__ __forceinline__ void st_rel_cluster_u32(unsigned addr, unsigned v) {
    asm volatile("st.release.cluster.shared::cluster.u32 [%0], %1;"
                 :: "r"(addr), "r"(v) : "memory");
}
__device__ __forceinline__ unsigned ld_acq_cluster(unsigned addr) {
    unsigned v;
    asm volatile("ld.acquire.cluster.shared::cta.u32 %0, [%1];"
                 : "=r"(v) : "r"(addr) : "memory");
    return v;
}
__device__ __forceinline__ void cluster_sync() {
    asm volatile("barrier.cluster.arrive.aligned;" ::: "memory");
    asm volatile("barrier.cluster.wait.aligned;" ::: "memory");
}
__device__ __forceinline__ unsigned ctarank() {
    unsigned r; asm("mov.u32 %0, %%cluster_ctarank;" : "=r"(r)); return r;
}

// ---- packed f32x2 helpers (sm_100+) -----------------------------------------
typedef unsigned long long u64;
__device__ __forceinline__ u64 pk2(float lo, float hi) {
    u64 r; asm("mov.b64 %0, {%1, %2};" : "=l"(r) : "f"(lo), "f"(hi)); return r;
}
__device__ __forceinline__ void upk2(u64 v, float& lo, float& hi) {
    asm("mov.b64 {%0, %1}, %2;" : "=f"(lo), "=f"(hi) : "l"(v));
}
__device__ __forceinline__ u64 fma2(u64 a, u64 b, u64 c) {
    u64 d; asm("fma.rn.f32x2 %0, %1, %2, %3;" : "=l"(d) : "l"(a), "l"(b), "l"(c));
    return d;
}
__device__ __forceinline__ u64 mul2(u64 a, u64 b) {
    u64 d; asm("mul.rn.f32x2 %0, %1, %2;" : "=l"(d) : "l"(a), "l"(b));
    return d;
}

// Warp-wide reduction of 32 per-lane values in 31 shuffles (5 dependent
// levels). On return, value j (summed over all lanes) is held by lane j.
__device__ __forceinline__ float fold32(float v[32], int lane) {
#pragma unroll
    for (int m = 16; m >= 1; m >>= 1) {
        const bool hi = (lane & m) != 0;
#pragma unroll
        for (int i = 0; i < m; i++) {
            float keep = hi ? v[i + m] : v[i];
            float send = hi ? v[i] : v[i + m];
            float recv = __shfl_xor_sync(0xffffffffu, send, m);
            v[i] = keep + recv;
        }
    }
    return v[0];
}

// pre[t][h] = Win[h,:]@x[t,:] + noise[t,h]/10
__global__ void pre_kernel(const float* __restrict__ noise,
                           const float* __restrict__ x,
                           const float* __restrict__ Win)
{
    int i = blockIdx.x * blockDim.x + threadIdx.x;
    if (i < TT * HH) {
        int t = i / HH, h = i - t * HH;
        float acc = noise[i] * 0.1f;
        const float* wr = &Win[h * 6];
        const float* xr = &x[t * 6];
#pragma unroll
        for (int k = 0; k < 6; k++) acc += wr[k] * xr[k];
        g_pre[i] = acc;
    }
}

// Peer-visible shared layout (fixed offsets: peer addr = peer_base + offset).
struct alignas(128) ShMsg {
    float    msg[2][NCTA][32];    // [A_t(0..15) | B_t(16..31)] per producer
    unsigned flg[2][NCTA];        // monotonic tags
};

__global__ void __launch_bounds__(TPB, 1) __cluster_dims__(NCTA, 1, 1)
snn_scan(const float* __restrict__ pin,    // [H,16]
         const float* __restrict__ pout,   // [H,16]
         const float* __restrict__ l,      // [16]
         const float* __restrict__ stau)   // [H]
{
    const int tid  = threadIdx.x;
    const int lane = tid & 31;
    const int warp = tid >> 5;
    const unsigned rank = ctarank();
    const int hbase = (int)rank * TPB + tid;

    __shared__ ShMsg sh;
    __shared__ __align__(128) float part[2][NW][32];   // local-only

    if (tid < 2 * NCTA) ((unsigned*)sh.flg)[tid] = 0u;
    __syncthreads();
    cluster_sync();   // zero-init visible before any remote store

    const unsigned msg_base = smem_u32(&sh.msg[0][0][0]);
    const unsigned flg_base = smem_u32(&sh.flg[0][0]);

    // ---- per-neuron constants (x4) in registers, packed by p-pairs ----
    const float drc    = 0.08208499862389880f;   // exp(-DT/TAU_R)
    const float c005dr = 0.005f * drc;

    float dd[NN], sg[NN], ic[NN];
    u64 lp2[NN][PP / 2], kA2[NN][PP / 2];
#pragma unroll
    for (int k = 0; k < NN; k++) {
        const int h = hbase + k * (NCTA * TPB);
        const float tau = 1.0f / (1.0f + expf(-stau[h])) * 0.03f + 0.02f;
        dd[k] = expf(-0.005f / tau);
        sg[k] = 2.5f / tau;                 // DT/(tau*TAU_R)
        ic[k] = tau * 80.0f;                // 1/(DT*sg)
        const float cA = 0.0125f / tau;     // DT*sg
#pragma unroll
        for (int j = 0; j < PP / 2; j++) {
            lp2[k][j] = pk2(l[2 * j]     * pin[h * PP + 2 * j],
                            l[2 * j + 1] * pin[h * PP + 2 * j + 1]);
            kA2[k][j] = pk2(pout[h * PP + 2 * j] * cA,
                            pout[h * PP + 2 * j + 1] * cA);
        }
    }

    float mem[NN], rr[NN], ss[NN], pre[NN];
    float vb[PP];   // B_t values (built in previous step's slack); B_0 = 0
#pragma unroll
    for (int k = 0; k < NN; k++) {
        mem[k] = 0.f; rr[k] = 0.f; ss[k] = 0.f;
        pre[k] = g_pre[hbase + k * (NCTA * TPB)];    // t = 0
    }
#pragma unroll
    for (int p = 0; p < PP; p++) vb[p] = 0.f;

    for (int t = 0; t < TT; t++) {
        // ===== consume: q[p] = Σ_c (A_{t-1}[c][p] + B_{t-1}[c][p]) =========
        float q = 0.f;
        if (t > 0) {
            const int sl = (t - 1) & 1;
            if (lane < NCTA) {
                const unsigned fa = flg_base + (unsigned)(sl * NCTA + lane) * 4u;
                while (ld_acq_cluster(fa) != (unsigned)t) {}
            }
            __syncwarp();
            const float* m = &sh.msg[sl][0][lane];
            float s0 = (m[0 * 32] + m[1 * 32]) + (m[2 * 32] + m[3 * 32]);
            float s1 = (m[4 * 32] + m[5 * 32]) + (m[6 * 32] + m[7 * 32]);
            float sum = s0 + s1;                 // 0-15: ΣA, 16-31: ΣB
            q = sum + __shfl_xor_sync(0xffffffffu, sum, 16);  // all lanes: q[lane&15]
        }

        // ============ I (packed dot) and membrane update ===================
        u64 acc2[NN];
#pragma unroll
        for (int k = 0; k < NN; k++) acc2[k] = pk2(pre[k], 0.f);
#pragma unroll
        for (int j = 0; j < PP / 2; j++) {
            const float qa = __shfl_sync(0xffffffffu, q, 2 * j);
            const float qb = __shfl_sync(0xffffffffu, q, 2 * j + 1);
            const u64 q2 = pk2(qa, qb);
#pragma unroll
            for (int k = 0; k < NN; k++)
                acc2[k] = fma2(lp2[k][j], q2, acc2[k]);
        }
        float f[NN];
#pragma unroll
        for (int k = 0; k < NN; k++) {
            float a, b;
            upk2(acc2[k], a, b);
            mem[k] = 0.9f * mem[k] + (a + b)
                   - ((mem[k] > 0.5f) ? 0.5f : 0.0f);
            f[k]   = (mem[k] > 0.5f) ? 1.0f : 0.0f;
        }

        // ============ A-half build (packed) + fold =========================
        float v[32];
        {
            const u64 f20 = pk2(f[0], f[0]);
            const u64 f21 = pk2(f[1], f[1]);
            const u64 f22 = pk2(f[2], f[2]);
            const u64 f23 = pk2(f[3], f[3]);
#pragma unroll
            for (int j = 0; j < PP / 2; j++) {
                u64 u = mul2(f23, kA2[3][j]);
                u = fma2(f22, kA2[2][j], u);
                u = fma2(f21, kA2[1][j], u);
                u = fma2(f20, kA2[0][j], u);
                upk2(u, v[2 * j], v[2 * j + 1]);
            }
        }
#pragma unroll
        for (int p = 0; p < PP; p++) v[16 + p] = vb[p];   // B_t from slack

        part[t & 1][warp][lane] = fold32(v, lane);

        // ============ distributed publish: warp w -> peers 2w, 2w+1 ========
        __syncthreads();   // all partials visible (drains STS)
        {
            const float* pp = &part[t & 1][0][lane];
            const float accm = (pp[0 * 32] + pp[1 * 32]) + (pp[2 * 32] + pp[3 * 32]);

            const unsigned my_msg = msg_base
                + (unsigned)(((t & 1) * NCTA + (int)rank) * 32 + lane) * 4u;
            const unsigned c0 = (unsigned)(warp * 2);
            st_cluster_f32(mapa_sh(my_msg, c0),      accm);
            st_cluster_f32(mapa_sh(my_msg, c0 + 1u), accm);
            __syncwarp();          // this warp's data stores before its flags
            if (lane < 2) {
                const unsigned my_flg = flg_base
                    + (unsigned)((t & 1) * NCTA + (int)rank) * 4u;
                st_rel_cluster_u32(mapa_sh(my_flg, c0 + (unsigned)lane),
                                   (unsigned)(t + 1));
            }
        }

        // ===== slack: state update, B_{t+1} build, traces, prefetch ========
        const int tn = (t + 1 < TT) ? (t + 1) : t;
        float rbn[NN];
#pragma unroll
        for (int k = 0; k < NN; k++) {
            ss[k]  = ss[k] * drc + f[k] * sg[k];
            rr[k]  = dd[k] * rr[k] + 0.005f * ss[k];
            rbn[k] = (dd[k] * rr[k] + c005dr * ss[k]) * ic[k];  // rbar_{t+1}/(DT*sg)
            g_r[t * HH + hbase + k * (NCTA * TPB)] = rr[k];
            pre[k] = g_pre[tn * HH + hbase + k * (NCTA * TPB)];
        }
        {
            const u64 r20 = pk2(rbn[0], rbn[0]);
            const u64 r21 = pk2(rbn[1], rbn[1]);
            const u64 r22 = pk2(rbn[2], rbn[2]);
            const u64 r23 = pk2(rbn[3], rbn[3]);
#pragma unroll
            for (int j = 0; j < PP / 2; j++) {
                u64 u = mul2(r23, kA2[3][j]);
                u = fma2(r22, kA2[2][j], u);
                u = fma2(r21, kA2[1][j], u);
                u = fma2(r20, kA2[0][j], u);
                upk2(u, vb[2 * j], vb[2 * j + 1]);   // B_{t+1} values
            }
        }
    }

    // No CTA may exit while peers' remote stores are in flight.
    cluster_sync();
}

// y[t,o] = Wout[o,:] @ r[t,:]  — one block per timestep, deterministic order.
__global__ void __launch_bounds__(256) y_kernel(const float* __restrict__ Wout,
                                                float* __restrict__ out)
{
    const int t   = blockIdx.x;
    const int tid = threadIdx.x;
    const int lane = tid & 31, warp = tid >> 5;
    float y0 = 0.f, y1 = 0.f;
#pragma unroll
    for (int j = 0; j < HH / 256; j++) {
        const int h  = tid + j * 256;
        const float rv = g_r[t * HH + h];
        y0 += Wout[h] * rv;
        y1 += Wout[HH + h] * rv;
    }
#pragma unroll
    for (int o = 16; o > 0; o >>= 1) {
        y0 += __shfl_xor_sync(0xffffffffu, y0, o);
        y1 += __shfl_xor_sync(0xffffffffu, y1, o);
    }
    __shared__ float s0[8], s1[8];
    if (lane == 0) { s0[warp] = y0; s1[warp] = y1; }
    __syncthreads();
    if (tid == 0) {
        float a0 = 0.f, a1 = 0.f;
#pragma unroll
        for (int w = 0; w < 8; w++) { a0 += s0[w]; a1 += s1[w]; }
        out[t * 2 + 0] = a0;
        out[t * 2 + 1] = a1;
    }
}

extern "C" void kernel_launch(void* const* d_in, const int* in_sizes, int n_in,
                              void* d_out, int out_size)
{
    const float* x     = (const float*)d_in[0];
    const float* noise = (const float*)d_in[1];
    const float* Win   = (const float*)d_in[2];
    const float* Wout  = (const float*)d_in[3];
    const float* pin   = (const float*)d_in[4];
    const float* pout  = (const float*)d_in[5];
    const float* l     = (const float*)d_in[6];
    const float* stau  = (const float*)d_in[7];
    float* out = (float*)d_out;

    pre_kernel<<<(TT * HH + 255) / 256, 256>>>(noise, x, Win);
    snn_scan<<<NCTA, TPB>>>(pin, pout, l, stau);
    y_kernel<<<TT, 256>>>(Wout, out);
}

// round 15
// speedup vs baseline: 1.3170x; 1.0120x over previous
#include <cuda_runtime.h>

#define TT   1000
#define HH   4096
#define PP   16
#define NCTA 8           // one cluster of 8 CTAs
#define TPB  128         // 4 warps; 4 contiguous neurons/thread: 8*128*4 = 4096
#define NW   (TPB / 32)
#define NN   4           // neurons per thread

// Scratch (device globals; no allocation). Rewritten identically every replay.
__device__ __align__(16) float g_pre[TT * HH];   // Win@x + noise/10
__device__ __align__(16) float g_r[TT * HH];     // r_t[h] trace (for y_kernel)

// ---- PTX helpers ------------------------------------------------------------
__device__ __forceinline__ unsigned smem_u32(const void* p) {
    return (unsigned)__cvta_generic_to_shared(p);
}
__device__ __forceinline__ unsigned mapa_sh(unsigned local, unsigned rank) {
    unsigned r;
    asm volatile("mapa.shared::cluster.u32 %0, %1, %2;" : "=r"(r) : "r"(local), "r"(rank));
    return r;
}
__device__ __forceinline__ void st_cluster_f32(unsigned addr, float v) {
    asm volatile("st.shared::cluster.f32 [%0], %1;" :: "r"(addr), "f"(v) : "memory");
}
__device__ __forceinline__ void st_rel_cluster_u32(unsigned addr, unsigned v) {
    asm volatile("st.release.cluster.shared::cluster.u32 [%0], %1;"
                 :: "r"(addr), "r"(v) : "memory");
}
__device__ __forceinline__ unsigned ld_acq_cluster(unsigned addr) {
    unsigned v;
    asm volatile("ld.acquire.cluster.shared::cta.u32 %0, [%1];"
                 : "=r"(v) : "r"(addr) : "memory");
    return v;
}
__device__ __forceinline__ void cluster_sync() {
    asm volatile("barrier.cluster.arrive.aligned;" ::: "memory");
    asm volatile("barrier.cluster.wait.aligned;" ::: "memory");
}
__device__ __forceinline__ unsigned ctarank() {
    unsigned r; asm("mov.u32 %0, %%cluster_ctarank;" : "=r"(r)); return r;
}

// ---- packed f32x2 helpers (sm_100+) -----------------------------------------
typedef unsigned long long u64;
__device__ __forceinline__ u64 pk2(float lo, float hi) {
    u64 r; asm("mov.b64 %0, {%1, %2};" : "=l"(r) : "f"(lo), "f"(hi)); return r;
}
__device__ __forceinline__ void upk2(u64 v, float& lo, float& hi) {
    asm("mov.b64 {%0, %1}, %2;" : "=f"(lo), "=f"(hi) : "l"(v));
}
__device__ __forceinline__ u64 fma2(u64 a, u64 b, u64 c) {
    u64 d; asm("fma.rn.f32x2 %0, %1, %2, %3;" : "=l"(d) : "l"(a), "l"(b), "l"(c));
    return d;
}
__device__ __forceinline__ u64 mul2(u64 a, u64 b) {
    u64 d; asm("mul.rn.f32x2 %0, %1, %2;" : "=l"(d) : "l"(a), "l"(b));
    return d;
}

// Warp-wide reduction of 32 per-lane values in 31 shuffles (5 dependent
// levels). On return, value j (summed over all lanes) is held by lane j.
__device__ __forceinline__ float fold32(float v[32], int lane) {
#pragma unroll
    for (int m = 16; m >= 1; m >>= 1) {
        const bool hi = (lane & m) != 0;
#pragma unroll
        for (int i = 0; i < m; i++) {
            float keep = hi ? v[i + m] : v[i];
            float send = hi ? v[i] : v[i + m];
            float recv = __shfl_xor_sync(0xffffffffu, send, m);
            v[i] = keep + recv;
        }
    }
    return v[0];
}

// pre[t][h] = Win[h,:]@x[t,:] + noise[t,h]/10
__global__ void pre_kernel(const float* __restrict__ noise,
                           const float* __restrict__ x,
                           const float* __restrict__ Win)
{
    int i = blockIdx.x * blockDim.x + threadIdx.x;
    if (i < TT * HH) {
        int t = i / HH, h = i - t * HH;
        float acc = noise[i] * 0.1f;
        const float* wr = &Win[h * 6];
        const float* xr = &x[t * 6];
#pragma unroll
        for (int k = 0; k < 6; k++) acc += wr[k] * xr[k];
        g_pre[i] = acc;
    }
}

// Peer-visible shared layout (fixed offsets: peer addr = peer_base + offset).
struct alignas(128) ShMsg {
    float    msg[2][NCTA][32];    // [A_t(0..15) | B_t(16..31)] per producer
    unsigned flg[2][NCTA];        // monotonic tags
};

__global__ void __launch_bounds__(TPB, 1) __cluster_dims__(NCTA, 1, 1)
snn_scan(const float* __restrict__ pin,    // [H,16]
         const float* __restrict__ pout,   // [H,16]
         const float* __restrict__ l,      // [16]
         const float* __restrict__ stau)   // [H]
{
    const int tid  = threadIdx.x;
    const int lane = tid & 31;
    const int warp = tid >> 5;
    const unsigned rank = ctarank();
    const int gtid = (int)rank * TPB + tid;   // 0..1023
    const int h0   = gtid * NN;               // 4 contiguous neurons

    __shared__ ShMsg sh;
    __shared__ __align__(128) float part[2][NW][32];   // local-only

    if (tid < 2 * NCTA) ((unsigned*)sh.flg)[tid] = 0u;
    __syncthreads();
    cluster_sync();   // zero-init visible before any remote store

    const unsigned msg_base = smem_u32(&sh.msg[0][0][0]);
    const unsigned flg_base = smem_u32(&sh.flg[0][0]);

    // ---- per-neuron constants (x4) in registers, packed by p-pairs ----
    const float drc    = 0.08208499862389880f;   // exp(-DT/TAU_R)
    const float c005dr = 0.005f * drc;

    float dd[NN], sg[NN], ic[NN];
    u64 lp2[NN][PP / 2], kA2[NN][PP / 2];
#pragma unroll
    for (int k = 0; k < NN; k++) {
        const int h = h0 + k;
        const float tau = 1.0f / (1.0f + expf(-stau[h])) * 0.03f + 0.02f;
        dd[k] = expf(-0.005f / tau);
        sg[k] = 2.5f / tau;                 // DT/(tau*TAU_R)
        ic[k] = tau * 80.0f;                // 1/(DT*sg)
        const float cA = 0.0125f / tau;     // DT*sg
#pragma unroll
        for (int j = 0; j < PP / 2; j++) {
            lp2[k][j] = pk2(l[2 * j]     * pin[h * PP + 2 * j],
                            l[2 * j + 1] * pin[h * PP + 2 * j + 1]);
            kA2[k][j] = pk2(pout[h * PP + 2 * j] * cA,
                            pout[h * PP + 2 * j + 1] * cA);
        }
    }

    const float4* __restrict__ gp4 = (const float4*)g_pre;
    float4*       __restrict__ gr4 = (float4*)g_r;

    float mem[NN], rr[NN], ss[NN];
    float vb[PP];   // B_t values (built in previous step's slack); B_0 = 0
    float4 pre4 = gp4[gtid];    // t = 0 (one LDG.128)
#pragma unroll
    for (int k = 0; k < NN; k++) { mem[k] = 0.f; rr[k] = 0.f; ss[k] = 0.f; }
#pragma unroll
    for (int p = 0; p < PP; p++) vb[p] = 0.f;

    for (int t = 0; t < TT; t++) {
        // ===== consume: q[p] = Σ_c (A_{t-1}[c][p] + B_{t-1}[c][p]) =========
        float q = 0.f;
        if (t > 0) {
            const int sl = (t - 1) & 1;
            if (lane < NCTA) {
                const unsigned fa = flg_base + (unsigned)(sl * NCTA + lane) * 4u;
                while (ld_acq_cluster(fa) != (unsigned)t) {}
            }
            __syncwarp();
            const float* m = &sh.msg[sl][0][lane];
            float s0 = (m[0 * 32] + m[1 * 32]) + (m[2 * 32] + m[3 * 32]);
            float s1 = (m[4 * 32] + m[5 * 32]) + (m[6 * 32] + m[7 * 32]);
            float sum = s0 + s1;                 // 0-15: ΣA, 16-31: ΣB
            q = sum + __shfl_xor_sync(0xffffffffu, sum, 16);  // all lanes: q[lane&15]
        }

        // ============ I (packed dot) and membrane update ===================
        const float prek[NN] = {pre4.x, pre4.y, pre4.z, pre4.w};
        u64 acc2[NN];
#pragma unroll
        for (int k = 0; k < NN; k++) acc2[k] = pk2(prek[k], 0.f);
#pragma unroll
        for (int j = 0; j < PP / 2; j++) {
            const float qa = __shfl_sync(0xffffffffu, q, 2 * j);
            const float qb = __shfl_sync(0xffffffffu, q, 2 * j + 1);
            const u64 q2 = pk2(qa, qb);
#pragma unroll
            for (int k = 0; k < NN; k++)
                acc2[k] = fma2(lp2[k][j], q2, acc2[k]);
        }
        float f[NN];
#pragma unroll
        for (int k = 0; k < NN; k++) {
            float a, b;
            upk2(acc2[k], a, b);
            mem[k] = 0.9f * mem[k] + (a + b)
                   - ((mem[k] > 0.5f) ? 0.5f : 0.0f);
            f[k]   = (mem[k] > 0.5f) ? 1.0f : 0.0f;
        }

        // ============ A-half build (packed) + fold =========================
        float v[32];
        {
            const u64 f20 = pk2(f[0], f[0]);
            const u64 f21 = pk2(f[1], f[1]);
            const u64 f22 = pk2(f[2], f[2]);
            const u64 f23 = pk2(f[3], f[3]);
#pragma unroll
            for (int j = 0; j < PP / 2; j++) {
                u64 u = mul2(f23, kA2[3][j]);
                u = fma2(f22, kA2[2][j], u);
                u = fma2(f21, kA2[1][j], u);
                u = fma2(f20, kA2[0][j], u);
                upk2(u, v[2 * j], v[2 * j + 1]);
            }
        }
#pragma unroll
        for (int p = 0; p < PP; p++) v[16 + p] = vb[p];   // B_t from slack

        const float vm = fold32(v, lane);   // my warp's partial, component <lane>
        part[t & 1][warp][lane] = vm;

        // ============ distributed publish: warp w -> peers 2w, 2w+1 ========
        __syncthreads();   // all partials visible (drains STS)
        {
            // combine: own partial from register + other 3 warps from smem
            float accm = vm;
#pragma unroll
            for (int w = 0; w < NW; w++)
                if (w != warp) accm += part[t & 1][w][lane];

            const unsigned my_msg = msg_base
                + (unsigned)(((t & 1) * NCTA + (int)rank) * 32 + lane) * 4u;
            const unsigned c0 = (unsigned)(warp * 2);
            st_cluster_f32(mapa_sh(my_msg, c0),      accm);
            st_cluster_f32(mapa_sh(my_msg, c0 + 1u), accm);
            __syncwarp();          // this warp's data stores before its flags
            if (lane < 2) {
                const unsigned my_flg = flg_base
                    + (unsigned)((t & 1) * NCTA + (int)rank) * 4u;
                st_rel_cluster_u32(mapa_sh(my_flg, c0 + (unsigned)lane),
                                   (unsigned)(t + 1));
            }
        }

        // ===== slack: state update, B_{t+1} build, trace + prefetch ========
        const int tn = (t + 1 < TT) ? (t + 1) : t;
        float rbn[NN];
#pragma unroll
        for (int k = 0; k < NN; k++) {
            ss[k]  = ss[k] * drc + f[k] * sg[k];
            rr[k]  = dd[k] * rr[k] + 0.005f * ss[k];
            rbn[k] = (dd[k] * rr[k] + c005dr * ss[k]) * ic[k];  // rbar_{t+1}/(DT*sg)
        }
        gr4[t * (HH / 4) + gtid] = make_float4(rr[0], rr[1], rr[2], rr[3]); // STG.128
        pre4 = gp4[tn * (HH / 4) + gtid];                                   // LDG.128
        {
            const u64 r20 = pk2(rbn[0], rbn[0]);
            const u64 r21 = pk2(rbn[1], rbn[1]);
            const u64 r22 = pk2(rbn[2], rbn[2]);
            const u64 r23 = pk2(rbn[3], rbn[3]);
#pragma unroll
            for (int j = 0; j < PP / 2; j++) {
                u64 u = mul2(r23, kA2[3][j]);
                u = fma2(r22, kA2[2][j], u);
                u = fma2(r21, kA2[1][j], u);
                u = fma2(r20, kA2[0][j], u);
                upk2(u, vb[2 * j], vb[2 * j + 1]);   // B_{t+1} values
            }
        }
    }

    // No CTA may exit while peers' remote stores are in flight.
    cluster_sync();
}

// y[t,o] = Wout[o,:] @ r[t,:]  — one block per timestep, deterministic order.
__global__ void __launch_bounds__(256) y_kernel(const float* __restrict__ Wout,
                                                float* __restrict__ out)
{
    const int t   = blockIdx.x;
    const int tid = threadIdx.x;
    const int lane = tid & 31, warp = tid >> 5;
    float y0 = 0.f, y1 = 0.f;
#pragma unroll
    for (int j = 0; j < HH / 256; j++) {
        const int h  = tid + j * 256;
        const float rv = g_r[t * HH + h];
        y0 += Wout[h] * rv;
        y1 += Wout[HH + h] * rv;
    }
#pragma unroll
    for (int o = 16; o > 0; o >>= 1) {
        y0 += __shfl_xor_sync(0xffffffffu, y0, o);
        y1 += __shfl_xor_sync(0xffffffffu, y1, o);
    }
    __shared__ float s0[8], s1[8];
    if (lane == 0) { s0[warp] = y0; s1[warp] = y1; }
    __syncthreads();
    if (tid == 0) {
        float a0 = 0.f, a1 = 0.f;
#pragma unroll
        for (int w = 0; w < 8; w++) { a0 += s0[w]; a1 += s1[w]; }
        out[t * 2 + 0] = a0;
        out[t * 2 + 1] = a1;
    }
}

extern "C" void kernel_launch(void* const* d_in, const int* in_sizes, int n_in,
                              void* d_out, int out_size)
{
    const float* x     = (const float*)d_in[0];
    const float* noise = (const float*)d_in[1];
    const float* Win   = (const float*)d_in[2];
    const float* Wout  = (const float*)d_in[3];
    const float* pin   = (const float*)d_in[4];
    const float* pout  = (const float*)d_in[5];
    const float* l     = (const float*)d_in[6];
    const float* stau  = (const float*)d_in[7];
    float* out = (float*)d_out;

    pre_kernel<<<(TT * HH + 255) / 256, 256>>>(noise, x, Win);
    snn_scan<<<NCTA, TPB>>>(pin, pout, l, stau);
    y_kernel<<<TT, 256>>>(Wout, out);
}